// round 2
// baseline (speedup 1.0000x reference)
#include <cuda_runtime.h>

#define BATCH   1024
#define IN_DIM  512
#define OUT_DIM 512
#define MOD_DIM 256
#define EPS_F   1e-8f

// Scratch (allocation-free rule: __device__ globals)
__device__ float g_colnorm[IN_DIM];
__device__ float g_y[BATCH * IN_DIM];

// ---------------------------------------------------------------------------
// Kernel 1: C[i] = sum_o weight[o][i]^2   (weight is [OUT_DIM, IN_DIM] row-major)
// grid = IN_DIM/128 blocks, 256 threads: 128 columns per block, 2 row-groups.
// ---------------------------------------------------------------------------
__global__ __launch_bounds__(256) void colnorm_kernel(const float* __restrict__ w) {
    int c  = blockIdx.x * 128 + (threadIdx.x & 127);
    int rg = threadIdx.x >> 7;  // 0 or 1
    float s = 0.f;
#pragma unroll 8
    for (int o = rg; o < OUT_DIM; o += 2) {
        float v = w[o * IN_DIM + c];
        s += v * v;
    }
    __shared__ float sh[256];
    sh[threadIdx.x] = s;
    __syncthreads();
    if (rg == 0) g_colnorm[c] = sh[threadIdx.x] + sh[threadIdx.x + 128];
}

// ---------------------------------------------------------------------------
// Tiled NT GEMM: C[M,N] = A[M,K] * B[N,K]^T, 64x64 tile, BK=16, 256 threads,
// 4x4 microtile per thread. Two fused epilogues:
//   EPI==0 : demodulation  C = x * s * rsqrt(s*s*colnorm + eps), s = acc + mod_b
//   EPI==1 : bias add      C = acc + bias
// All dims here are multiples of tile sizes; no bounds checks needed.
// ---------------------------------------------------------------------------
template <int EPI>
__global__ __launch_bounds__(256)
void gemm_nt(const float* __restrict__ A, const float* __restrict__ Bmat,
             float* __restrict__ C, int M, int N, int K,
             const float* __restrict__ xin, const float* __restrict__ addv,
             const float* __restrict__ cn)
{
    __shared__ float As[16][64];
    __shared__ float Bs[16][64];

    const int tid = threadIdx.x;
    const int m0 = blockIdx.y * 64;
    const int n0 = blockIdx.x * 64;
    const int tx = tid & 15;        // 16 col-threads
    const int ty = tid >> 4;        // 16 row-threads
    const int lr = tid >> 2;        // 0..63  : row within tile for loading
    const int lk = (tid & 3) << 2;  // 0,4,8,12 : k offset for float4 load

    const float* Ap = A    + (size_t)(m0 + lr) * K + lk;
    const float* Bp = Bmat + (size_t)(n0 + lr) * K + lk;

    float acc[4][4] = {};

    for (int k0 = 0; k0 < K; k0 += 16) {
        float4 av = *(const float4*)(Ap + k0);
        float4 bv = *(const float4*)(Bp + k0);
        As[lk + 0][lr] = av.x; As[lk + 1][lr] = av.y;
        As[lk + 2][lr] = av.z; As[lk + 3][lr] = av.w;
        Bs[lk + 0][lr] = bv.x; Bs[lk + 1][lr] = bv.y;
        Bs[lk + 2][lr] = bv.z; Bs[lk + 3][lr] = bv.w;
        __syncthreads();

#pragma unroll
        for (int k = 0; k < 16; k++) {
            float4 a4 = *(const float4*)&As[k][ty << 2];
            float4 b4 = *(const float4*)&Bs[k][tx << 2];
            float a[4] = {a4.x, a4.y, a4.z, a4.w};
            float b[4] = {b4.x, b4.y, b4.z, b4.w};
#pragma unroll
            for (int i = 0; i < 4; i++)
#pragma unroll
                for (int j = 0; j < 4; j++)
                    acc[i][j] += a[i] * b[j];
        }
        __syncthreads();
    }

    const int row = m0 + (ty << 2);
    const int col = n0 + (tx << 2);

    if (EPI == 0) {
        float4 mb = *(const float4*)(addv + col);   // mod_b
        float4 c4 = *(const float4*)(cn + col);     // colnorm
#pragma unroll
        for (int i = 0; i < 4; i++) {
            float4 xv = *(const float4*)(xin + (size_t)(row + i) * N + col);
            float4 o; float s;
            s = acc[i][0] + mb.x; o.x = xv.x * s * rsqrtf(s * s * c4.x + EPS_F);
            s = acc[i][1] + mb.y; o.y = xv.y * s * rsqrtf(s * s * c4.y + EPS_F);
            s = acc[i][2] + mb.z; o.z = xv.z * s * rsqrtf(s * s * c4.z + EPS_F);
            s = acc[i][3] + mb.w; o.w = xv.w * s * rsqrtf(s * s * c4.w + EPS_F);
            *(float4*)(C + (size_t)(row + i) * N + col) = o;
        }
    } else {
        float4 bv = *(const float4*)(addv + col);   // bias
#pragma unroll
        for (int i = 0; i < 4; i++) {
            float4 o;
            o.x = acc[i][0] + bv.x; o.y = acc[i][1] + bv.y;
            o.z = acc[i][2] + bv.z; o.w = acc[i][3] + bv.w;
            *(float4*)(C + (size_t)(row + i) * N + col) = o;
        }
    }
}

// ---------------------------------------------------------------------------
extern "C" void kernel_launch(void* const* d_in, const int* in_sizes, int n_in,
                              void* d_out, int out_size) {
    const float* modulations = (const float*)d_in[0];   // [1024, 256]
    const float* x           = (const float*)d_in[1];   // [1024, 512]
    const float* weight      = (const float*)d_in[2];   // [512, 512]
    const float* bias        = (const float*)d_in[3];   // [512]
    const float* mod_w       = (const float*)d_in[4];   // [512, 256]
    const float* mod_b       = (const float*)d_in[5];   // [512]
    float* out = (float*)d_out;                          // [1024, 512]

    float* y  = nullptr;
    float* cn = nullptr;
    cudaGetSymbolAddress((void**)&y,  g_y);
    cudaGetSymbolAddress((void**)&cn, g_colnorm);

    // 1) per-column weight norms
    colnorm_kernel<<<IN_DIM / 128, 256>>>(weight);

    // 2) scales GEMM + fused demodulation -> y[b,i] = x*s*rsqrt(s^2*C+eps)
    gemm_nt<0><<<dim3(IN_DIM / 64, BATCH / 64), 256>>>(
        modulations, mod_w, y, BATCH, IN_DIM, MOD_DIM, x, mod_b, cn);

    // 3) out = y @ weight^T + bias
    gemm_nt<1><<<dim3(OUT_DIM / 64, BATCH / 64), 256>>>(
        y, weight, out, BATCH, OUT_DIM, IN_DIM, nullptr, bias, nullptr);
}

// round 3
// speedup vs baseline: 1.1045x; 1.1045x over previous
#include <cuda_runtime.h>

#define BATCH   1024
#define IN_DIM  512
#define OUT_DIM 512
#define MOD_DIM 256
#define EPS_F   1e-8f

// Scratch (allocation-free rule: __device__ globals)
__device__ float g_colnorm[IN_DIM];
__device__ float g_y[BATCH * IN_DIM];

// ---------------------------------------------------------------------------
// Kernel 1: colnorm[i] = sum_o weight[o][i]^2, weight [OUT_DIM, IN_DIM] row-major.
// grid = 16 row-chunks of 32 rows; block = 256 threads.
// Thread layout: ct = tid & 127 -> handles columns [4ct, 4ct+4) via float4;
//                rg = tid >> 7  -> rows rowbase+rg, step 2 (16 rows each).
// Per-block partial for all 512 columns, smem-combined, atomicAdd to global.
// g_colnorm is zeroed by cudaMemsetAsync before launch.
// ---------------------------------------------------------------------------
__global__ __launch_bounds__(256) void colnorm_kernel(const float* __restrict__ w) {
    const int ct = threadIdx.x & 127;
    const int rg = threadIdx.x >> 7;
    const int rowbase = blockIdx.x * 32 + rg;

    float4 s = make_float4(0.f, 0.f, 0.f, 0.f);
#pragma unroll
    for (int r = 0; r < 16; r++) {
        const int o = rowbase + r * 2;
        float4 v = *(const float4*)(w + (size_t)o * IN_DIM + ct * 4);
        s.x += v.x * v.x; s.y += v.y * v.y; s.z += v.z * v.z; s.w += v.w * v.w;
    }

    __shared__ float4 sh[256];
    sh[threadIdx.x] = s;
    __syncthreads();
    if (rg == 0) {
        float4 a = sh[threadIdx.x];
        float4 b = sh[threadIdx.x + 128];
        atomicAdd(&g_colnorm[ct * 4 + 0], a.x + b.x);
        atomicAdd(&g_colnorm[ct * 4 + 1], a.y + b.y);
        atomicAdd(&g_colnorm[ct * 4 + 2], a.z + b.z);
        atomicAdd(&g_colnorm[ct * 4 + 3], a.w + b.w);
    }
}

// ---------------------------------------------------------------------------
// Tiled NT GEMM: C[M,N] = A[M,K] * B[N,K]^T, 64x64 tile, BK=16, 256 threads,
// 4x4 microtile per thread. Two fused epilogues:
//   EPI==0 : demodulation  C = x * s * rsqrt(s*s*colnorm + eps), s = acc + mod_b
//   EPI==1 : bias add      C = acc + bias
// All dims are multiples of tile sizes; no bounds checks needed.
// ---------------------------------------------------------------------------
template <int EPI>
__global__ __launch_bounds__(256)
void gemm_nt(const float* __restrict__ A, const float* __restrict__ Bmat,
             float* __restrict__ C, int M, int N, int K,
             const float* __restrict__ xin, const float* __restrict__ addv,
             const float* __restrict__ cn)
{
    __shared__ float As[16][64];
    __shared__ float Bs[16][64];

    const int tid = threadIdx.x;
    const int m0 = blockIdx.y * 64;
    const int n0 = blockIdx.x * 64;
    const int tx = tid & 15;        // 16 col-threads
    const int ty = tid >> 4;        // 16 row-threads
    const int lr = tid >> 2;        // 0..63  : row within tile for loading
    const int lk = (tid & 3) << 2;  // 0,4,8,12 : k offset for float4 load

    const float* Ap = A    + (size_t)(m0 + lr) * K + lk;
    const float* Bp = Bmat + (size_t)(n0 + lr) * K + lk;

    float acc[4][4] = {};

    for (int k0 = 0; k0 < K; k0 += 16) {
        float4 av = *(const float4*)(Ap + k0);
        float4 bv = *(const float4*)(Bp + k0);
        As[lk + 0][lr] = av.x; As[lk + 1][lr] = av.y;
        As[lk + 2][lr] = av.z; As[lk + 3][lr] = av.w;
        Bs[lk + 0][lr] = bv.x; Bs[lk + 1][lr] = bv.y;
        Bs[lk + 2][lr] = bv.z; Bs[lk + 3][lr] = bv.w;
        __syncthreads();

#pragma unroll
        for (int k = 0; k < 16; k++) {
            float4 a4 = *(const float4*)&As[k][ty << 2];
            float4 b4 = *(const float4*)&Bs[k][tx << 2];
            float a[4] = {a4.x, a4.y, a4.z, a4.w};
            float b[4] = {b4.x, b4.y, b4.z, b4.w};
#pragma unroll
            for (int i = 0; i < 4; i++)
#pragma unroll
                for (int j = 0; j < 4; j++)
                    acc[i][j] += a[i] * b[j];
        }
        __syncthreads();
    }

    const int row = m0 + (ty << 2);
    const int col = n0 + (tx << 2);

    if (EPI == 0) {
        float4 mb = *(const float4*)(addv + col);   // mod_b
        float4 c4 = *(const float4*)(cn + col);     // colnorm
#pragma unroll
        for (int i = 0; i < 4; i++) {
            float4 xv = *(const float4*)(xin + (size_t)(row + i) * N + col);
            float4 o; float s;
            s = acc[i][0] + mb.x; o.x = xv.x * s * rsqrtf(s * s * c4.x + EPS_F);
            s = acc[i][1] + mb.y; o.y = xv.y * s * rsqrtf(s * s * c4.y + EPS_F);
            s = acc[i][2] + mb.z; o.z = xv.z * s * rsqrtf(s * s * c4.z + EPS_F);
            s = acc[i][3] + mb.w; o.w = xv.w * s * rsqrtf(s * s * c4.w + EPS_F);
            *(float4*)(C + (size_t)(row + i) * N + col) = o;
        }
    } else {
        float4 bv = *(const float4*)(addv + col);   // bias
#pragma unroll
        for (int i = 0; i < 4; i++) {
            float4 o;
            o.x = acc[i][0] + bv.x; o.y = acc[i][1] + bv.y;
            o.z = acc[i][2] + bv.z; o.w = acc[i][3] + bv.w;
            *(float4*)(C + (size_t)(row + i) * N + col) = o;
        }
    }
}

// ---------------------------------------------------------------------------
extern "C" void kernel_launch(void* const* d_in, const int* in_sizes, int n_in,
                              void* d_out, int out_size) {
    const float* modulations = (const float*)d_in[0];   // [1024, 256]
    const float* x           = (const float*)d_in[1];   // [1024, 512]
    const float* weight      = (const float*)d_in[2];   // [512, 512]
    const float* bias        = (const float*)d_in[3];   // [512]
    const float* mod_w       = (const float*)d_in[4];   // [512, 256]
    const float* mod_b       = (const float*)d_in[5];   // [512]
    float* out = (float*)d_out;                          // [1024, 512]

    float* y  = nullptr;
    float* cn = nullptr;
    cudaGetSymbolAddress((void**)&y,  g_y);
    cudaGetSymbolAddress((void**)&cn, g_colnorm);

    // 1) per-column weight norms (zeroed, then atomic-accumulated by 16 blocks)
    cudaMemsetAsync(cn, 0, IN_DIM * sizeof(float));
    colnorm_kernel<<<16, 256>>>(weight);

    // 2) scales GEMM + fused demodulation -> y[b,i] = x*s*rsqrt(s^2*C+eps)
    gemm_nt<0><<<dim3(IN_DIM / 64, BATCH / 64), 256>>>(
        modulations, mod_w, y, BATCH, IN_DIM, MOD_DIM, x, mod_b, cn);

    // 3) out = y @ weight^T + bias
    gemm_nt<1><<<dim3(OUT_DIM / 64, BATCH / 64), 256>>>(
        y, weight, out, BATCH, OUT_DIM, IN_DIM, nullptr, bias, nullptr);
}

// round 4
// speedup vs baseline: 1.2649x; 1.1452x over previous
#include <cuda_runtime.h>

#define BATCH   1024
#define IN_DIM  512
#define OUT_DIM 512
#define MOD_DIM 256
#define EPS_F   1e-8f

// Scratch (allocation-free rule: __device__ globals)
__device__ float g_colnorm[IN_DIM];
__device__ float g_y[BATCH * IN_DIM];

// ---------------------------------------------------------------------------
// Kernel 1: colnorm[i] = sum_o weight[o][i]^2, weight [OUT_DIM, IN_DIM].
// grid = 64 blocks x 8 rows; 256 threads; float4 column loads; smem combine;
// atomicAdd into g_colnorm (zeroed by cudaMemsetAsync).
// ---------------------------------------------------------------------------
__global__ __launch_bounds__(256) void colnorm_kernel(const float* __restrict__ w) {
    const int ct = threadIdx.x & 127;
    const int rg = threadIdx.x >> 7;
    const int rowbase = blockIdx.x * 8 + rg;

    float4 s = make_float4(0.f, 0.f, 0.f, 0.f);
#pragma unroll
    for (int r = 0; r < 4; r++) {
        const int o = rowbase + r * 2;
        float4 v = *(const float4*)(w + (size_t)o * IN_DIM + ct * 4);
        s.x += v.x * v.x; s.y += v.y * v.y; s.z += v.z * v.z; s.w += v.w * v.w;
    }

    __shared__ float4 sh[256];
    sh[threadIdx.x] = s;
    __syncthreads();
    if (rg == 0) {
        float4 a = sh[threadIdx.x];
        float4 b = sh[threadIdx.x + 128];
        atomicAdd(&g_colnorm[ct * 4 + 0], a.x + b.x);
        atomicAdd(&g_colnorm[ct * 4 + 1], a.y + b.y);
        atomicAdd(&g_colnorm[ct * 4 + 2], a.z + b.z);
        atomicAdd(&g_colnorm[ct * 4 + 3], a.w + b.w);
    }
}

// ---------------------------------------------------------------------------
// Double-buffered tiled NT GEMM: C[M,N] = A[M,K]*B[N,K]^T.
// 64x64 tile, BK=32, 256 threads, 4x4 microtile, 2-stage smem pipeline.
//   EPI==0 : demodulation  C = x * s * rsqrt(s*s*colnorm + eps), s = acc+mod_b
//   EPI==1 : bias add      C = acc + bias
// ---------------------------------------------------------------------------
template <int EPI>
__global__ __launch_bounds__(256)
void gemm_nt(const float* __restrict__ A, const float* __restrict__ Bmat,
             float* __restrict__ C, int M, int N, int K,
             const float* __restrict__ xin, const float* __restrict__ addv,
             const float* __restrict__ cn)
{
    __shared__ float As[2][32][64];
    __shared__ float Bs[2][32][64];

    const int tid = threadIdx.x;
    const int m0 = blockIdx.y * 64;
    const int n0 = blockIdx.x * 64;
    const int tx = tid & 15;        // 16 col-threads
    const int ty = tid >> 4;        // 16 row-threads
    const int lr = tid >> 2;        // 0..63 : tile row for loading
    const int lk = (tid & 3) << 2;  // 0,4,8,12 : k offset (float4), +16 for hi

    const float* Ap = A    + (size_t)(m0 + lr) * K + lk;
    const float* Bp = Bmat + (size_t)(n0 + lr) * K + lk;

    // prologue: tile 0
    float4 a0 = *(const float4*)(Ap);
    float4 a1 = *(const float4*)(Ap + 16);
    float4 b0 = *(const float4*)(Bp);
    float4 b1 = *(const float4*)(Bp + 16);
    As[0][lk + 0][lr] = a0.x; As[0][lk + 1][lr] = a0.y;
    As[0][lk + 2][lr] = a0.z; As[0][lk + 3][lr] = a0.w;
    As[0][lk + 16][lr] = a1.x; As[0][lk + 17][lr] = a1.y;
    As[0][lk + 18][lr] = a1.z; As[0][lk + 19][lr] = a1.w;
    Bs[0][lk + 0][lr] = b0.x; Bs[0][lk + 1][lr] = b0.y;
    Bs[0][lk + 2][lr] = b0.z; Bs[0][lk + 3][lr] = b0.w;
    Bs[0][lk + 16][lr] = b1.x; Bs[0][lk + 17][lr] = b1.y;
    Bs[0][lk + 18][lr] = b1.z; Bs[0][lk + 19][lr] = b1.w;
    __syncthreads();

    float acc[4][4] = {};
    const int nt = K >> 5;

    for (int t = 0; t < nt; ++t) {
        const int cur = t & 1;
        const int nxt = cur ^ 1;

        // prefetch next tile (overlaps with compute below)
        if (t + 1 < nt) {
            const int off = (t + 1) << 5;
            a0 = *(const float4*)(Ap + off);
            a1 = *(const float4*)(Ap + off + 16);
            b0 = *(const float4*)(Bp + off);
            b1 = *(const float4*)(Bp + off + 16);
        }

#pragma unroll
        for (int k = 0; k < 32; k++) {
            float4 a4 = *(const float4*)&As[cur][k][ty << 2];
            float4 b4 = *(const float4*)&Bs[cur][k][tx << 2];
            float a[4] = {a4.x, a4.y, a4.z, a4.w};
            float b[4] = {b4.x, b4.y, b4.z, b4.w};
#pragma unroll
            for (int i = 0; i < 4; i++)
#pragma unroll
                for (int j = 0; j < 4; j++)
                    acc[i][j] += a[i] * b[j];
        }

        if (t + 1 < nt) {
            As[nxt][lk + 0][lr] = a0.x; As[nxt][lk + 1][lr] = a0.y;
            As[nxt][lk + 2][lr] = a0.z; As[nxt][lk + 3][lr] = a0.w;
            As[nxt][lk + 16][lr] = a1.x; As[nxt][lk + 17][lr] = a1.y;
            As[nxt][lk + 18][lr] = a1.z; As[nxt][lk + 19][lr] = a1.w;
            Bs[nxt][lk + 0][lr] = b0.x; Bs[nxt][lk + 1][lr] = b0.y;
            Bs[nxt][lk + 2][lr] = b0.z; Bs[nxt][lk + 3][lr] = b0.w;
            Bs[nxt][lk + 16][lr] = b1.x; Bs[nxt][lk + 17][lr] = b1.y;
            Bs[nxt][lk + 18][lr] = b1.z; Bs[nxt][lk + 19][lr] = b1.w;
        }
        __syncthreads();
    }

    const int row = m0 + (ty << 2);
    const int col = n0 + (tx << 2);

    if (EPI == 0) {
        float4 mb = *(const float4*)(addv + col);   // mod_b
        float4 c4 = *(const float4*)(cn + col);     // colnorm
#pragma unroll
        for (int i = 0; i < 4; i++) {
            float4 xv = *(const float4*)(xin + (size_t)(row + i) * N + col);
            float4 o; float s;
            s = acc[i][0] + mb.x; o.x = xv.x * s * rsqrtf(s * s * c4.x + EPS_F);
            s = acc[i][1] + mb.y; o.y = xv.y * s * rsqrtf(s * s * c4.y + EPS_F);
            s = acc[i][2] + mb.z; o.z = xv.z * s * rsqrtf(s * s * c4.z + EPS_F);
            s = acc[i][3] + mb.w; o.w = xv.w * s * rsqrtf(s * s * c4.w + EPS_F);
            *(float4*)(C + (size_t)(row + i) * N + col) = o;
        }
    } else {
        float4 bv = *(const float4*)(addv + col);   // bias
#pragma unroll
        for (int i = 0; i < 4; i++) {
            float4 o;
            o.x = acc[i][0] + bv.x; o.y = acc[i][1] + bv.y;
            o.z = acc[i][2] + bv.z; o.w = acc[i][3] + bv.w;
            *(float4*)(C + (size_t)(row + i) * N + col) = o;
        }
    }
}

// ---------------------------------------------------------------------------
extern "C" void kernel_launch(void* const* d_in, const int* in_sizes, int n_in,
                              void* d_out, int out_size) {
    const float* modulations = (const float*)d_in[0];   // [1024, 256]
    const float* x           = (const float*)d_in[1];   // [1024, 512]
    const float* weight      = (const float*)d_in[2];   // [512, 512]
    const float* bias        = (const float*)d_in[3];   // [512]
    const float* mod_w       = (const float*)d_in[4];   // [512, 256]
    const float* mod_b       = (const float*)d_in[5];   // [512]
    float* out = (float*)d_out;                          // [1024, 512]

    float* y  = nullptr;
    float* cn = nullptr;
    cudaGetSymbolAddress((void**)&y,  g_y);
    cudaGetSymbolAddress((void**)&cn, g_colnorm);

    // 1) per-column weight norms
    cudaMemsetAsync(cn, 0, IN_DIM * sizeof(float));
    colnorm_kernel<<<64, 256>>>(weight);

    // 2) scales GEMM + fused demodulation -> y[b,i] = x*s*rsqrt(s^2*C+eps)
    gemm_nt<0><<<dim3(IN_DIM / 64, BATCH / 64), 256>>>(
        modulations, mod_w, y, BATCH, IN_DIM, MOD_DIM, x, mod_b, cn);

    // 3) out = y @ weight^T + bias
    gemm_nt<1><<<dim3(OUT_DIM / 64, BATCH / 64), 256>>>(
        y, weight, out, BATCH, OUT_DIM, IN_DIM, nullptr, bias, nullptr);
}

// round 6
// speedup vs baseline: 1.3556x; 1.0718x over previous
#include <cuda_runtime.h>

#define BATCH   1024
#define IN_DIM  512
#define OUT_DIM 512
#define MOD_DIM 256
#define EPS_F   1e-8f
#define NBLK    128

// Scratch (allocation-free rule: __device__ globals)
__device__ float g_y[BATCH * IN_DIM];
__device__ unsigned int g_count;                 // returns to 0 after each barrier
__device__ volatile unsigned int g_gen;          // monotonically increasing phase

struct Smem {
    float As[2][32][64];
    float Bs[2][32][64];
    float cn[64];
};

// Sense-reversing grid barrier. Safe across graph replays (g_count self-resets,
// g_gen is a free-running phase). All NBLK blocks are co-resident (1 wave).
__device__ __forceinline__ void grid_barrier() {
    __threadfence();          // publish this thread's prior writes device-wide
    __syncthreads();
    if (threadIdx.x == 0) {
        unsigned int gen = g_gen;
        if (atomicAdd(&g_count, 1) == NBLK - 1) {
            g_count = 0;
            __threadfence();
            g_gen = gen + 1;
        } else {
            while (g_gen == gen) { }
        }
        __threadfence();      // acquire side
    }
    __syncthreads();
}

// ---------------------------------------------------------------------------
// Double-buffered 64x64 NT GEMM tile: C[m0:+64, n0:+64] += A[M,K]*B[N,K]^T.
// BK=32, 256 threads, 4x4 microtile.
//   EPI==0 : demodulation  C = x * s * rsqrt(s*s*cn + eps), s = acc + addv
//   EPI==1 : bias add      C = acc + addv
// ---------------------------------------------------------------------------
template <int EPI>
__device__ __forceinline__
void gemm_tile(Smem& sm, const float* __restrict__ A, const float* __restrict__ B,
               float* __restrict__ C, int N, int K, int m0, int n0,
               const float* __restrict__ xin, const float* __restrict__ addv)
{
    const int tid = threadIdx.x;
    const int tx = tid & 15;
    const int ty = tid >> 4;
    const int lr = tid >> 2;
    const int lk = (tid & 3) << 2;

    const float* Ap = A + (size_t)(m0 + lr) * K + lk;
    const float* Bp = B + (size_t)(n0 + lr) * K + lk;

    float4 a0 = *(const float4*)(Ap);
    float4 a1 = *(const float4*)(Ap + 16);
    float4 b0 = *(const float4*)(Bp);
    float4 b1 = *(const float4*)(Bp + 16);
    sm.As[0][lk + 0][lr] = a0.x; sm.As[0][lk + 1][lr] = a0.y;
    sm.As[0][lk + 2][lr] = a0.z; sm.As[0][lk + 3][lr] = a0.w;
    sm.As[0][lk + 16][lr] = a1.x; sm.As[0][lk + 17][lr] = a1.y;
    sm.As[0][lk + 18][lr] = a1.z; sm.As[0][lk + 19][lr] = a1.w;
    sm.Bs[0][lk + 0][lr] = b0.x; sm.Bs[0][lk + 1][lr] = b0.y;
    sm.Bs[0][lk + 2][lr] = b0.z; sm.Bs[0][lk + 3][lr] = b0.w;
    sm.Bs[0][lk + 16][lr] = b1.x; sm.Bs[0][lk + 17][lr] = b1.y;
    sm.Bs[0][lk + 18][lr] = b1.z; sm.Bs[0][lk + 19][lr] = b1.w;
    __syncthreads();

    float acc[4][4] = {};
    const int nt = K >> 5;

    for (int t = 0; t < nt; ++t) {
        const int cur = t & 1;
        const int nxt = cur ^ 1;

        if (t + 1 < nt) {
            const int off = (t + 1) << 5;
            a0 = *(const float4*)(Ap + off);
            a1 = *(const float4*)(Ap + off + 16);
            b0 = *(const float4*)(Bp + off);
            b1 = *(const float4*)(Bp + off + 16);
        }

#pragma unroll
        for (int k = 0; k < 32; k++) {
            float4 a4 = *(const float4*)&sm.As[cur][k][ty << 2];
            float4 b4 = *(const float4*)&sm.Bs[cur][k][tx << 2];
            float a[4] = {a4.x, a4.y, a4.z, a4.w};
            float b[4] = {b4.x, b4.y, b4.z, b4.w};
#pragma unroll
            for (int i = 0; i < 4; i++)
#pragma unroll
                for (int j = 0; j < 4; j++)
                    acc[i][j] += a[i] * b[j];
        }

        if (t + 1 < nt) {
            sm.As[nxt][lk + 0][lr] = a0.x; sm.As[nxt][lk + 1][lr] = a0.y;
            sm.As[nxt][lk + 2][lr] = a0.z; sm.As[nxt][lk + 3][lr] = a0.w;
            sm.As[nxt][lk + 16][lr] = a1.x; sm.As[nxt][lk + 17][lr] = a1.y;
            sm.As[nxt][lk + 18][lr] = a1.z; sm.As[nxt][lk + 19][lr] = a1.w;
            sm.Bs[nxt][lk + 0][lr] = b0.x; sm.Bs[nxt][lk + 1][lr] = b0.y;
            sm.Bs[nxt][lk + 2][lr] = b0.z; sm.Bs[nxt][lk + 3][lr] = b0.w;
            sm.Bs[nxt][lk + 16][lr] = b1.x; sm.Bs[nxt][lk + 17][lr] = b1.y;
            sm.Bs[nxt][lk + 18][lr] = b1.z; sm.Bs[nxt][lk + 19][lr] = b1.w;
        }
        __syncthreads();
    }

    const int row = m0 + (ty << 2);
    const int col = n0 + (tx << 2);

    if (EPI == 0) {
        float4 mb = *(const float4*)(addv + col);        // mod_b
        float4 c4 = *(const float4*)&sm.cn[tx << 2];     // colnorm (block-local)
#pragma unroll
        for (int i = 0; i < 4; i++) {
            float4 xv = *(const float4*)(xin + (size_t)(row + i) * N + col);
            float4 o; float s;
            s = acc[i][0] + mb.x; o.x = xv.x * s * rsqrtf(s * s * c4.x + EPS_F);
            s = acc[i][1] + mb.y; o.y = xv.y * s * rsqrtf(s * s * c4.y + EPS_F);
            s = acc[i][2] + mb.z; o.z = xv.z * s * rsqrtf(s * s * c4.z + EPS_F);
            s = acc[i][3] + mb.w; o.w = xv.w * s * rsqrtf(s * s * c4.w + EPS_F);
            *(float4*)(C + (size_t)(row + i) * N + col) = o;
        }
    } else {
        float4 bv = *(const float4*)(addv + col);        // bias
#pragma unroll
        for (int i = 0; i < 4; i++) {
            float4 o;
            o.x = acc[i][0] + bv.x; o.y = acc[i][1] + bv.y;
            o.z = acc[i][2] + bv.z; o.w = acc[i][3] + bv.w;
            *(float4*)(C + (size_t)(row + i) * N + col) = o;
        }
    }
}

// ---------------------------------------------------------------------------
// One persistent launch, grid = 128 (one wave):
//   prelude : per-block colnorm for its 64 IN-columns (no atomics, no memset)
//   phase 1 : y = demod(modulations @ mod_w^T + mod_b)   [uses prelude colnorm]
//   grid barrier
//   phase 2 : out = y @ weight^T + bias
// ---------------------------------------------------------------------------
__global__ __launch_bounds__(256)
void fused_kernel(const float* __restrict__ modulations,
                  const float* __restrict__ x,
                  const float* __restrict__ weight,
                  const float* __restrict__ bias,
                  const float* __restrict__ mod_w,
                  const float* __restrict__ mod_b,
                  float* __restrict__ out)
{
    __shared__ Smem sm;
    const int tid = threadIdx.x;
    const int bx = blockIdx.x & 7;    // column-tile (IN or OUT, both 8 tiles)
    const int by = blockIdx.x >> 3;   // batch-tile (16 tiles)

    // ---- colnorm prelude: cn[j] = sum_o weight[o][64*bx + j]^2, j in [0,64)
    {
        const int cg = tid & 15;      // 16 groups of 4 columns
        const int rt = tid >> 4;      // 16 row-threads, 32 rows each
        const float* wp = weight + 64 * bx + cg * 4;
        float4 s = make_float4(0.f, 0.f, 0.f, 0.f);
#pragma unroll 8
        for (int r = rt; r < OUT_DIM; r += 16) {
            float4 v = *(const float4*)(wp + (size_t)r * IN_DIM);
            s.x += v.x * v.x; s.y += v.y * v.y; s.z += v.z * v.z; s.w += v.w * v.w;
        }
        float4* red = (float4*)sm.As;     // reuse As as reduction scratch
        red[tid] = s;                     // tid = rt*16 + cg
        __syncthreads();
#pragma unroll
        for (int st = 8; st >= 1; st >>= 1) {
            if (rt < st) {
                float4 m = red[rt * 16 + cg];
                float4 o = red[(rt + st) * 16 + cg];
                m.x += o.x; m.y += o.y; m.z += o.z; m.w += o.w;
                red[rt * 16 + cg] = m;
            }
            __syncthreads();
        }
        if (rt == 0) {
            float4 v = red[cg];
            sm.cn[cg * 4 + 0] = v.x; sm.cn[cg * 4 + 1] = v.y;
            sm.cn[cg * 4 + 2] = v.z; sm.cn[cg * 4 + 3] = v.w;
        }
        __syncthreads();
    }

    // ---- phase 1: y = demod(mod @ mod_w^T)
    gemm_tile<0>(sm, modulations, mod_w, g_y, IN_DIM, MOD_DIM,
                 by * 64, bx * 64, x, mod_b);

    grid_barrier();

    // ---- phase 2: out = y @ weight^T + bias
    gemm_tile<1>(sm, g_y, weight, out, OUT_DIM, IN_DIM,
                 by * 64, bx * 64, nullptr, bias);
}

// ---------------------------------------------------------------------------
extern "C" void kernel_launch(void* const* d_in, const int* in_sizes, int n_in,
                              void* d_out, int out_size) {
    const float* modulations = (const float*)d_in[0];   // [1024, 256]
    const float* x           = (const float*)d_in[1];   // [1024, 512]
    const float* weight      = (const float*)d_in[2];   // [512, 512]
    const float* bias        = (const float*)d_in[3];   // [512]
    const float* mod_w       = (const float*)d_in[4];   // [512, 256]
    const float* mod_b       = (const float*)d_in[5];   // [512]
    float* out = (float*)d_out;                          // [1024, 512]

    fused_kernel<<<NBLK, 256>>>(modulations, x, weight, bias, mod_w, mod_b, out);
}

// round 9
// speedup vs baseline: 1.6578x; 1.2229x over previous
#include <cuda_runtime.h>
#include <cuda_bf16.h>
#include <cstdint>

#define BATCH   1024
#define IN_DIM  512
#define OUT_DIM 512
#define MOD_DIM 256
#define EPS_F   1e-8f
#define NBLK    128

// ---------------- device scratch (allocation-free rule) ----------------
__device__ __align__(16) __nv_bfloat16 g_mod_hi[BATCH * MOD_DIM];
__device__ __align__(16) __nv_bfloat16 g_mod_lo[BATCH * MOD_DIM];
__device__ __align__(16) __nv_bfloat16 g_mw_hi[IN_DIM * MOD_DIM];
__device__ __align__(16) __nv_bfloat16 g_mw_lo[IN_DIM * MOD_DIM];
__device__ __align__(16) __nv_bfloat16 g_w_hi[OUT_DIM * IN_DIM];
__device__ __align__(16) __nv_bfloat16 g_w_lo[OUT_DIM * IN_DIM];
__device__ __align__(16) __nv_bfloat16 g_y_hi[BATCH * IN_DIM];
__device__ __align__(16) __nv_bfloat16 g_y_lo[BATCH * IN_DIM];
__device__ float g_cn[IN_DIM];
__device__ unsigned int g_count;
__device__ volatile unsigned int g_gen;

// ---------------- base-ISA PTX helpers (sm_80+, valid on compute_103) ----------
__device__ __forceinline__ uint32_t smem_u32(const void* p) {
    uint32_t a;
    asm("{ .reg .u64 t; cvta.to.shared.u64 t, %1; cvt.u32.u64 %0, t; }" : "=r"(a) : "l"(p));
    return a;
}
__device__ __forceinline__ void cp16(uint32_t dst, const void* src) {
    asm volatile("cp.async.cg.shared.global [%0], [%1], 16;" :: "r"(dst), "l"(src));
}
#define CP_COMMIT() asm volatile("cp.async.commit_group;" ::: "memory")
#define CP_WAIT(n)  asm volatile("cp.async.wait_group %0;" :: "n"(n) : "memory")

__device__ __forceinline__ void ldsm4(uint32_t* r, uint32_t addr) {
    asm volatile("ldmatrix.sync.aligned.m8n8.x4.shared.b16 {%0,%1,%2,%3}, [%4];"
        : "=r"(r[0]), "=r"(r[1]), "=r"(r[2]), "=r"(r[3]) : "r"(addr));
}
__device__ __forceinline__ void ldsm2(uint32_t* r, uint32_t addr) {
    asm volatile("ldmatrix.sync.aligned.m8n8.x2.shared.b16 {%0,%1}, [%2];"
        : "=r"(r[0]), "=r"(r[1]) : "r"(addr));
}
__device__ __forceinline__ void mma_bf16(float* d, const uint32_t* a, const uint32_t* b) {
    asm volatile("mma.sync.aligned.m16n8k16.row.col.f32.bf16.bf16.f32 "
        "{%0,%1,%2,%3}, {%4,%5,%6,%7}, {%8,%9}, {%0,%1,%2,%3};"
        : "+f"(d[0]), "+f"(d[1]), "+f"(d[2]), "+f"(d[3])
        : "r"(a[0]), "r"(a[1]), "r"(a[2]), "r"(a[3]), "r"(b[0]), "r"(b[1]));
}

// Grid barrier (validated in R6). All NBLK blocks co-resident (one wave).
__device__ __forceinline__ void grid_barrier() {
    __threadfence();
    __syncthreads();
    if (threadIdx.x == 0) {
        unsigned int gen = g_gen;
        if (atomicAdd(&g_count, 1) == NBLK - 1) {
            g_count = 0;
            __threadfence();
            g_gen = gen + 1;
        } else {
            while (g_gen == gen) { }
        }
        __threadfence();
    }
    __syncthreads();
}

// ---------------- smem layout: 2 buffers x {Ah, Al, Bh, Bl} tiles -------------
// Tile = 64 rows x 32 bf16, row padded to 40 bf16 (80 B) -> ldmatrix phase-
// conflict-free (8-row groups hit distinct 16B bank groups).
#define PADB  80
#define TILEB (64 * PADB)     // 5120 B
#define BUFB  (4 * TILEB)     // 20480 B

// Load one K=32 chunk of Ah/Al/Bh/Bl into smem buffer via cp.async (8x16B/thr).
__device__ __forceinline__ void load_chunk(
    uint32_t sb,
    const __nv_bfloat16* __restrict__ Ah, const __nv_bfloat16* __restrict__ Al,
    const __nv_bfloat16* __restrict__ Bh, const __nv_bfloat16* __restrict__ Bl,
    int m0, int n0, int K, int kc, int tid)
{
    const int row = tid >> 1;
    const int h   = tid & 1;
    const uint32_t so = (uint32_t)row * PADB + h * 32;
    const size_t ao = (size_t)(m0 + row) * K + kc + h * 16;
    const size_t bo = (size_t)(n0 + row) * K + kc + h * 16;
    cp16(sb + 0 * TILEB + so,      Ah + ao);
    cp16(sb + 0 * TILEB + so + 16, Ah + ao + 8);
    cp16(sb + 1 * TILEB + so,      Al + ao);
    cp16(sb + 1 * TILEB + so + 16, Al + ao + 8);
    cp16(sb + 2 * TILEB + so,      Bh + bo);
    cp16(sb + 2 * TILEB + so + 16, Bh + bo + 8);
    cp16(sb + 3 * TILEB + so,      Bl + bo);
    cp16(sb + 3 * TILEB + so + 16, Bl + bo + 8);
}

// ---------------------------------------------------------------------------
// 64x64 block tile NT GEMM, 4 warps in 2x2 (warp tile 32x32), mma m16n8k16,
// 3-term bf16 compensation, fp32 accumulate, cp.async double buffer.
//   EPI==0 : demod -> y_hi/y_lo bf16   EPI==1 : bias -> fp32 out
// ---------------------------------------------------------------------------
template <int EPI>
__device__ __forceinline__ void gemm_phase(
    uint32_t smb,
    const __nv_bfloat16* __restrict__ Ah, const __nv_bfloat16* __restrict__ Al,
    const __nv_bfloat16* __restrict__ Bh, const __nv_bfloat16* __restrict__ Bl,
    int K, int m0, int n0,
    const float* __restrict__ xin, const float* __restrict__ addv,
    float* __restrict__ outp)
{
    const int tid  = threadIdx.x;
    const int wid  = tid >> 5;
    const int lane = tid & 31;
    const int wm = (wid >> 1) * 32;     // warp row offset in tile
    const int wn = (wid & 1) * 32;      // warp col offset in tile

    float acc[2][4][4] = {};

    const int nch = K >> 5;
    load_chunk(smb, Ah, Al, Bh, Bl, m0, n0, K, 0, tid);
    CP_COMMIT();

    // lane-derived smem fragment offsets (bytes)
    const uint32_t aoff = (uint32_t)(wm + (lane & 15)) * PADB + (lane & 16);
    const uint32_t boff = (uint32_t)(wn + (lane & 7)) * PADB + ((lane & 8) * 2);

    for (int c = 0; c < nch; c++) {
        const uint32_t cb = smb + (uint32_t)(c & 1) * BUFB;
        if (c + 1 < nch) {
            load_chunk(smb + (uint32_t)((c + 1) & 1) * BUFB,
                       Ah, Al, Bh, Bl, m0, n0, K, (c + 1) << 5, tid);
            CP_COMMIT();
            CP_WAIT(1);
        } else {
            CP_WAIT(0);
        }
        __syncthreads();

#pragma unroll
        for (int k16 = 0; k16 < 32; k16 += 16) {
            const uint32_t kb = (uint32_t)k16 * 2;
            uint32_t ah[2][4], al[2][4], bh[4][2], bl[4][2];
#pragma unroll
            for (int mi = 0; mi < 2; mi++) {
                ldsm4(ah[mi], cb + 0 * TILEB + aoff + (uint32_t)mi * 16 * PADB + kb);
                ldsm4(al[mi], cb + 1 * TILEB + aoff + (uint32_t)mi * 16 * PADB + kb);
            }
#pragma unroll
            for (int ni = 0; ni < 4; ni++) {
                ldsm2(bh[ni], cb + 2 * TILEB + boff + (uint32_t)ni * 8 * PADB + kb);
                ldsm2(bl[ni], cb + 3 * TILEB + boff + (uint32_t)ni * 8 * PADB + kb);
            }
#pragma unroll
            for (int mi = 0; mi < 2; mi++)
#pragma unroll
                for (int ni = 0; ni < 4; ni++) {
                    mma_bf16(acc[mi][ni], ah[mi], bh[ni]);
                    mma_bf16(acc[mi][ni], ah[mi], bl[ni]);
                    mma_bf16(acc[mi][ni], al[mi], bh[ni]);
                }
        }
        __syncthreads();
    }

    // ---- epilogue. D frag: {c0,c1}=row g, cols 2t..; {c2,c3}=row g+8.
    const int g = lane >> 2, t = lane & 3;

    if (EPI == 0) {
        float2 mb[4], cn2[4];
#pragma unroll
        for (int ni = 0; ni < 4; ni++) {
            const int col = n0 + wn + 8 * ni + 2 * t;
            mb[ni]  = *(const float2*)(addv + col);
            cn2[ni] = *(const float2*)(g_cn + col);
        }
#pragma unroll
        for (int mi = 0; mi < 2; mi++)
#pragma unroll
            for (int hf = 0; hf < 2; hf++) {
                const int row = m0 + wm + 16 * mi + g + 8 * hf;
#pragma unroll
                for (int ni = 0; ni < 4; ni++) {
                    const int col = n0 + wn + 8 * ni + 2 * t;
                    float2 xv = *(const float2*)(xin + (size_t)row * IN_DIM + col);
                    const float s0 = acc[mi][ni][2 * hf + 0] + mb[ni].x;
                    const float s1 = acc[mi][ni][2 * hf + 1] + mb[ni].y;
                    const float y0 = xv.x * s0 * rsqrtf(s0 * s0 * cn2[ni].x + EPS_F);
                    const float y1 = xv.y * s1 * rsqrtf(s1 * s1 * cn2[ni].y + EPS_F);
                    const __nv_bfloat16 h0 = __float2bfloat16_rn(y0);
                    const __nv_bfloat16 h1 = __float2bfloat16_rn(y1);
                    const __nv_bfloat16 l0 = __float2bfloat16_rn(y0 - __bfloat162float(h0));
                    const __nv_bfloat16 l1 = __float2bfloat16_rn(y1 - __bfloat162float(h1));
                    *(__nv_bfloat162*)(g_y_hi + (size_t)row * IN_DIM + col) = __halves2bfloat162(h0, h1);
                    *(__nv_bfloat162*)(g_y_lo + (size_t)row * IN_DIM + col) = __halves2bfloat162(l0, l1);
                }
            }
    } else {
        float2 bv[4];
#pragma unroll
        for (int ni = 0; ni < 4; ni++)
            bv[ni] = *(const float2*)(addv + n0 + wn + 8 * ni + 2 * t);
#pragma unroll
        for (int mi = 0; mi < 2; mi++)
#pragma unroll
            for (int hf = 0; hf < 2; hf++) {
                const int row = m0 + wm + 16 * mi + g + 8 * hf;
#pragma unroll
                for (int ni = 0; ni < 4; ni++) {
                    const int col = n0 + wn + 8 * ni + 2 * t;
                    float2 o;
                    o.x = acc[mi][ni][2 * hf + 0] + bv[ni].x;
                    o.y = acc[mi][ni][2 * hf + 1] + bv[ni].y;
                    *(float2*)(outp + (size_t)row * OUT_DIM + col) = o;
                }
            }
    }
}

// ---------------------------------------------------------------------------
// Persistent kernel, grid=128, 128 threads:
//   phase0 : blocks 0-7 colnorm; blocks 8-127 fp32->hi/lo bf16 splits
//   barrier
//   phase1 : y = demod(mod @ mod_w^T + mod_b)      [warp mma, 3-term bf16]
//   barrier
//   phase2 : out = y @ weight^T + bias             [warp mma, 3-term bf16]
// ---------------------------------------------------------------------------
#define N_MOD4 (BATCH * MOD_DIM / 4)
#define N_MW4  (IN_DIM * MOD_DIM / 4)
#define N_W4   (OUT_DIM * IN_DIM / 4)
#define N_TOT4 (N_MOD4 + N_MW4 + N_W4)

__global__ __launch_bounds__(128)
void fused_kernel(const float* __restrict__ modulations,
                  const float* __restrict__ x,
                  const float* __restrict__ weight,
                  const float* __restrict__ bias,
                  const float* __restrict__ mod_w,
                  const float* __restrict__ mod_b,
                  float* __restrict__ out)
{
    __shared__ __align__(16) char smem[2 * BUFB];
    __shared__ float cnsh[128];
    const uint32_t smb = smem_u32(smem);
    const int tid = threadIdx.x;

    // ---- phase 0
    if (blockIdx.x < 8) {
        const int c  = blockIdx.x * 64 + (tid & 63);
        const int rg = tid >> 6;     // 0..1
        float s = 0.f;
#pragma unroll 8
        for (int r = rg; r < OUT_DIM; r += 2) {
            const float v = weight[(size_t)r * IN_DIM + c];
            s += v * v;
        }
        cnsh[tid] = s;
        __syncthreads();
        if (rg == 0) g_cn[c] = cnsh[tid] + cnsh[tid + 64];
    } else {
        const int stride = 120 * 128;
        for (int tq = (blockIdx.x - 8) * 128 + tid; tq < N_TOT4; tq += stride) {
            const float* src;
            __nv_bfloat16 *ph, *pl;
            size_t e;
            if (tq < N_MOD4)              { src = modulations; ph = g_mod_hi; pl = g_mod_lo; e = (size_t)tq * 4; }
            else if (tq < N_MOD4 + N_MW4) { src = mod_w;       ph = g_mw_hi;  pl = g_mw_lo;  e = (size_t)(tq - N_MOD4) * 4; }
            else                          { src = weight;      ph = g_w_hi;   pl = g_w_lo;   e = (size_t)(tq - N_MOD4 - N_MW4) * 4; }
            float4 v = *(const float4*)(src + e);
            float f[4] = {v.x, v.y, v.z, v.w};
            __nv_bfloat16 h[4], l[4];
#pragma unroll
            for (int i = 0; i < 4; i++) {
                h[i] = __float2bfloat16_rn(f[i]);
                l[i] = __float2bfloat16_rn(f[i] - __bfloat162float(h[i]));
            }
            *(__nv_bfloat162*)(ph + e)     = __halves2bfloat162(h[0], h[1]);
            *(__nv_bfloat162*)(ph + e + 2) = __halves2bfloat162(h[2], h[3]);
            *(__nv_bfloat162*)(pl + e)     = __halves2bfloat162(l[0], l[1]);
            *(__nv_bfloat162*)(pl + e + 2) = __halves2bfloat162(l[2], l[3]);
        }
    }

    grid_barrier();

    const int bx = blockIdx.x & 7;    // 8 col-tiles of 64 (both phases)
    const int by = blockIdx.x >> 3;   // 16 batch-tiles of 64

    // ---- phase 1: y = demod(mod @ mod_w^T + mod_b)
    gemm_phase<0>(smb, g_mod_hi, g_mod_lo, g_mw_hi, g_mw_lo,
                  MOD_DIM, by * 64, bx * 64, x, mod_b, nullptr);

    grid_barrier();

    // ---- phase 2: out = y @ weight^T + bias
    gemm_phase<1>(smb, g_y_hi, g_y_lo, g_w_hi, g_w_lo,
                  IN_DIM, by * 64, bx * 64, nullptr, bias, out);
}

// ---------------------------------------------------------------------------
extern "C" void kernel_launch(void* const* d_in, const int* in_sizes, int n_in,
                              void* d_out, int out_size) {
    const float* modulations = (const float*)d_in[0];   // [1024, 256]
    const float* x           = (const float*)d_in[1];   // [1024, 512]
    const float* weight      = (const float*)d_in[2];   // [512, 512]
    const float* bias        = (const float*)d_in[3];   // [512]
    const float* mod_w       = (const float*)d_in[4];   // [512, 256]
    const float* mod_b       = (const float*)d_in[5];   // [512]
    float* out = (float*)d_out;                          // [1024, 512]

    fused_kernel<<<NBLK, 128>>>(modulations, x, weight, bias, mod_w, mod_b, out);
}